// round 10
// baseline (speedup 1.0000x reference)
#include <cuda_runtime.h>

namespace {
constexpr int NX = 256, NY = 256, NZ = 128;
constexpr int NZ4 = NZ / 4, XS4 = NY * NZ4, FS4 = NX * XS4;

constexpr float CVc = 717.0f;
constexpr float MUc = 1.8e-5f, KTHc = 0.025f, Gc = 9.8f;
constexpr float Rg  = 287.0f;

constexpr double DXd = 1.0 / NX, DYd = 1.0 / NY, DZd = 1.0 / (NZ - 1);
constexpr float inv2dx = (float)(0.5 / DXd);
constexpr float inv2dy = (float)(0.5 / DYd);
constexpr float inv2dz = (float)(0.5 / DZd);
constexpr float invdx2 = (float)(1.0 / (DXd * DXd));
constexpr float invdy2 = (float)(1.0 / (DYd * DYd));
constexpr float invdz2 = (float)(1.0 / (DZd * DZd));
constexpr float kTco   = KTHc / CVc;

__device__ __forceinline__ float4 operator+(float4 a, float4 b){ return make_float4(a.x+b.x, a.y+b.y, a.z+b.z, a.w+b.w); }
__device__ __forceinline__ float4 operator-(float4 a, float4 b){ return make_float4(a.x-b.x, a.y-b.y, a.z-b.z, a.w-b.w); }
__device__ __forceinline__ float4 operator*(float4 a, float4 b){ return make_float4(a.x*b.x, a.y*b.y, a.z*b.z, a.w*b.w); }
__device__ __forceinline__ float4 operator*(float4 a, float s){ return make_float4(a.x*s, a.y*s, a.z*s, a.w*s); }
__device__ __forceinline__ float4 operator*(float s, float4 a){ return a * s; }

__device__ __forceinline__ float4 zm_of(float4 a){
    float p = __shfl_up_sync(0xffffffffu, a.w, 1);
    return make_float4(p, a.x, a.y, a.z);
}
__device__ __forceinline__ float4 zp_of(float4 a){
    float n = __shfl_down_sync(0xffffffffu, a.x, 1);
    return make_float4(a.y, a.z, a.w, n);
}
__device__ __forceinline__ float4 inv4(float4 a){
    return make_float4(1.0f/a.x, 1.0f/a.y, 1.0f/a.z, 1.0f/a.w);
}
__device__ __forceinline__ float4 maskwall(float4 v, bool lo, bool hi){
    if (lo) v.x = 0.0f;
    if (hi) v.w = 0.0f;
    return v;
}
__device__ __forceinline__ void prefetchL2(const void* p){
    asm volatile("prefetch.global.L2 [%0];" :: "l"(p));
}

__global__ __launch_bounds__(256, 2)
void rbx2_kernel(const float4* __restrict__ s, float4* __restrict__ o)
{
    const int lane = threadIdx.x;                     // z chunk (4 z per lane)
    const int y  = (blockIdx.x << 3) | threadIdx.y;   // 8 y rows per block
    const int x0 = blockIdx.y << 1;                   // 2 x-points per thread

    const int bxm = ((x0 + NX - 1) & (NX - 1)) * XS4;
    const int b0  = x0 * XS4;
    const int b1  = (x0 + 1) * XS4;
    const int bxq = ((x0 + 2) & (NX - 1)) * XS4;

    const int rc_  = y * NZ4 + lane;
    const int rym_ = ((y + NY - 1) & (NY - 1)) * NZ4 + lane;
    const int ryp_ = ((y + 1)      & (NY - 1)) * NZ4 + lane;

    const bool lo = (lane == 0);
    const bool hi = (lane == 31);

    // ---- L2 prefetch of the leading-edge (x+2) plane: no registers consumed ----
    #pragma unroll
    for (int f = 0; f < 6; f++) prefetchL2(s + f*FS4 + bxq + rc_);

    // ================= phase 1a: rho, T -> p, dp*, rinv, drou, u planes =================
    float4 u_xm, u0, u1, u_xq;                 // persist into u phase
    float4 rinv0, rinv1, Tc0, Tc1;
    float4 dpdx0, dpdx1, dpdy0, dpdy1, dpdz0, dpdz1;
    {
        const float4 r_xm = s[3*FS4 + bxm + rc_], r_0 = s[3*FS4 + b0 + rc_];
        const float4 r_1  = s[3*FS4 + b1  + rc_], r_xq = s[3*FS4 + bxq + rc_];
        const float4 T_xm = s[4*FS4 + bxm + rc_];
        Tc0 = s[4*FS4 + b0 + rc_];
        Tc1 = s[4*FS4 + b1 + rc_];
        const float4 T_xq = s[4*FS4 + bxq + rc_];

        u_xm = s[0*FS4 + bxm + rc_]; u0 = s[0*FS4 + b0 + rc_];
        u1   = s[0*FS4 + b1  + rc_]; u_xq = s[0*FS4 + bxq + rc_];

        // continuity (x-flux only)
        __stcs(&o[3*FS4 + b0 + rc_], (r_xm * u_xm - r_1 * u1) * inv2dx);
        __stcs(&o[3*FS4 + b1 + rc_], (r_0  * u0   - r_xq * u_xq) * inv2dx);

        rinv0 = inv4(r_0);
        rinv1 = inv4(r_1);

        const float4 p_xm = (Rg) * r_xm * T_xm;
        const float4 p0   = (Rg) * r_0  * Tc0;
        const float4 p1   = (Rg) * r_1  * Tc1;
        const float4 p_xq = (Rg) * r_xq * T_xq;

        dpdx0 = (p1   - p_xm) * inv2dx;
        dpdx1 = (p_xq - p0)   * inv2dx;
        dpdz0 = (zp_of(p0) - zm_of(p0)) * inv2dz;
        dpdz1 = (zp_of(p1) - zm_of(p1)) * inv2dz;

        // y-pressure (load r,T at y-neighbors, form p, drop)
        float4 ra = s[3*FS4 + b0 + rym_], Ta = s[4*FS4 + b0 + rym_];
        float4 rb = s[3*FS4 + b0 + ryp_], Tb = s[4*FS4 + b0 + ryp_];
        dpdy0 = (rb * Tb - ra * Ta) * (Rg * inv2dy);
        ra = s[3*FS4 + b1 + rym_]; Ta = s[4*FS4 + b1 + rym_];
        rb = s[3*FS4 + b1 + ryp_]; Tb = s[4*FS4 + b1 + ryp_];
        dpdy1 = (rb * Tb - ra * Ta) * (Rg * inv2dy);
    }

    // ================= phase 1b: dT (reload T neighbors — L1 hot) + v,w centers ========
    float4 vc0, vc1, wc0, wc1;                 // persist as advection velocities
    {
        vc0 = s[1*FS4 + b0 + rc_]; vc1 = s[1*FS4 + b1 + rc_];
        wc0 = s[2*FS4 + b0 + rc_]; wc1 = s[2*FS4 + b1 + rc_];

        const float4 Txm  = s[4*FS4 + bxm + rc_], Txq  = s[4*FS4 + bxq + rc_];
        const float4 Tym0 = s[4*FS4 + b0 + rym_], Typ0 = s[4*FS4 + b0 + ryp_];
        const float4 Tym1 = s[4*FS4 + b1 + rym_], Typ1 = s[4*FS4 + b1 + ryp_];
        const float4 Tzm0 = zm_of(Tc0), Tzp0 = zp_of(Tc0);
        const float4 Tzm1 = zm_of(Tc1), Tzp1 = zp_of(Tc1);

        const float4 lapT0 = (Tc1 + Txm - Tc0*2.0f)*invdx2 + (Typ0 + Tym0 - Tc0*2.0f)*invdy2 + (Tzp0 + Tzm0 - Tc0*2.0f)*invdz2;
        const float4 advT0 = u0*((Tc1 - Txm)*inv2dx) + vc0*((Typ0 - Tym0)*inv2dy) + wc0*((Tzp0 - Tzm0)*inv2dz);
        __stcs(&o[4*FS4 + b0 + rc_], maskwall((lapT0 * kTco) * rinv0 - advT0, lo, hi));

        const float4 lapT1 = (Txq + Tc0 - Tc1*2.0f)*invdx2 + (Typ1 + Tym1 - Tc1*2.0f)*invdy2 + (Tzp1 + Tzm1 - Tc1*2.0f)*invdz2;
        const float4 advT1 = u1*((Txq - Tc0)*inv2dx) + vc1*((Typ1 - Tym1)*inv2dy) + wc1*((Tzp1 - Tzm1)*inv2dz);
        __stcs(&o[4*FS4 + b1 + rc_], maskwall((lapT1 * kTco) * rinv1 - advT1, lo, hi));
    }

    // ================= phase 2: u =================
    {
        const float4 uym0 = s[0*FS4 + b0 + rym_], uyp0 = s[0*FS4 + b0 + ryp_];
        const float4 uym1 = s[0*FS4 + b1 + rym_], uyp1 = s[0*FS4 + b1 + ryp_];
        const float4 uzm0 = zm_of(u0), uzp0 = zp_of(u0);
        const float4 uzm1 = zm_of(u1), uzp1 = zp_of(u1);

        const float4 lapU0 = (u1 + u_xm - u0*2.0f)*invdx2 + (uyp0 + uym0 - u0*2.0f)*invdy2 + (uzp0 + uzm0 - u0*2.0f)*invdz2;
        const float4 advU0 = u0*((u1 - u_xm)*inv2dx) + vc0*((uyp0 - uym0)*inv2dy) + wc0*((uzp0 - uzm0)*inv2dz);
        __stcs(&o[0*FS4 + b0 + rc_], maskwall((lapU0 * MUc - dpdx0) * rinv0 - advU0, lo, hi));

        const float4 lapU1 = (u_xq + u0 - u1*2.0f)*invdx2 + (uyp1 + uym1 - u1*2.0f)*invdy2 + (uzp1 + uzm1 - u1*2.0f)*invdz2;
        const float4 advU1 = u1*((u_xq - u0)*inv2dx) + vc1*((uyp1 - uym1)*inv2dy) + wc1*((uzp1 - uzm1)*inv2dz);
        __stcs(&o[0*FS4 + b1 + rc_], maskwall((lapU1 * MUc - dpdx1) * rinv1 - advU1, lo, hi));
    }

    // ================= phase 3: v =================
    {
        const float4 v_xm = s[1*FS4 + bxm + rc_], v_xq = s[1*FS4 + bxq + rc_];
        const float4 vym0 = s[1*FS4 + b0 + rym_], vyp0 = s[1*FS4 + b0 + ryp_];
        const float4 vym1 = s[1*FS4 + b1 + rym_], vyp1 = s[1*FS4 + b1 + ryp_];
        const float4 vzm0 = zm_of(vc0), vzp0 = zp_of(vc0);
        const float4 vzm1 = zm_of(vc1), vzp1 = zp_of(vc1);

        const float4 lapV0 = (vc1 + v_xm - vc0*2.0f)*invdx2 + (vyp0 + vym0 - vc0*2.0f)*invdy2 + (vzp0 + vzm0 - vc0*2.0f)*invdz2;
        const float4 advV0 = u0*((vc1 - v_xm)*inv2dx) + vc0*((vyp0 - vym0)*inv2dy) + wc0*((vzp0 - vzm0)*inv2dz);
        __stcs(&o[1*FS4 + b0 + rc_], maskwall((lapV0 * MUc - dpdy0) * rinv0 - advV0, lo, hi));

        const float4 lapV1 = (v_xq + vc0 - vc1*2.0f)*invdx2 + (vyp1 + vym1 - vc1*2.0f)*invdy2 + (vzp1 + vzm1 - vc1*2.0f)*invdz2;
        const float4 advV1 = u1*((v_xq - vc0)*inv2dx) + vc1*((vyp1 - vym1)*inv2dy) + wc1*((vzp1 - vzm1)*inv2dz);
        __stcs(&o[1*FS4 + b1 + rc_], maskwall((lapV1 * MUc - dpdy1) * rinv1 - advV1, lo, hi));
    }

    // ================= phase 4: w  ((-G*rho)/rho == -G) =================
    {
        const float4 w_xm = s[2*FS4 + bxm + rc_], w_xq = s[2*FS4 + bxq + rc_];
        const float4 wym0 = s[2*FS4 + b0 + rym_], wyp0 = s[2*FS4 + b0 + ryp_];
        const float4 wym1 = s[2*FS4 + b1 + rym_], wyp1 = s[2*FS4 + b1 + ryp_];
        const float4 wzm0 = zm_of(wc0), wzp0 = zp_of(wc0);
        const float4 wzm1 = zm_of(wc1), wzp1 = zp_of(wc1);

        const float4 lapW0 = (wc1 + w_xm - wc0*2.0f)*invdx2 + (wyp0 + wym0 - wc0*2.0f)*invdy2 + (wzp0 + wzm0 - wc0*2.0f)*invdz2;
        const float4 advW0 = u0*((wc1 - w_xm)*inv2dx) + vc0*((wyp0 - wym0)*inv2dy) + wc0*((wzp0 - wzm0)*inv2dz);
        float4 dw0 = (lapW0 * MUc - dpdz0) * rinv0 - advW0;
        dw0 = make_float4(dw0.x - Gc, dw0.y - Gc, dw0.z - Gc, dw0.w - Gc);
        __stcs(&o[2*FS4 + b0 + rc_], maskwall(dw0, lo, hi));

        const float4 lapW1 = (w_xq + wc0 - wc1*2.0f)*invdx2 + (wyp1 + wym1 - wc1*2.0f)*invdy2 + (wzp1 + wzm1 - wc1*2.0f)*invdz2;
        const float4 advW1 = u1*((w_xq - wc0)*inv2dx) + vc1*((wyp1 - wym1)*inv2dy) + wc1*((wzp1 - wzm1)*inv2dz);
        float4 dw1 = (lapW1 * MUc - dpdz1) * rinv1 - advW1;
        dw1 = make_float4(dw1.x - Gc, dw1.y - Gc, dw1.z - Gc, dw1.w - Gc);
        __stcs(&o[2*FS4 + b1 + rc_], maskwall(dw1, lo, hi));
    }

    // ================= phase 5: c (one-sided z at walls, NOT masked) =================
    {
        const float4 c_xm = s[5*FS4 + bxm + rc_], c0 = s[5*FS4 + b0 + rc_];
        const float4 c1   = s[5*FS4 + b1  + rc_], c_xq = s[5*FS4 + bxq + rc_];
        const float4 cym0 = s[5*FS4 + b0 + rym_], cyp0 = s[5*FS4 + b0 + ryp_];
        const float4 cym1 = s[5*FS4 + b1 + rym_], cyp1 = s[5*FS4 + b1 + ryp_];

        const float4 czm0 = zm_of(c0), czp0 = zp_of(c0);
        const float4 czm1 = zm_of(c1), czp1 = zp_of(c1);

        float4 dcdz0 = (czp0 - czm0) * inv2dz;
        float4 dcdz1 = (czp1 - czm1) * inv2dz;
        if (lo) {
            dcdz0.x = (-3.0f * c0.x + 4.0f * c0.y - c0.z) * inv2dz;
            dcdz1.x = (-3.0f * c1.x + 4.0f * c1.y - c1.z) * inv2dz;
        }
        if (hi) {
            dcdz0.w = ( 3.0f * c0.w - 4.0f * c0.z + c0.y) * inv2dz;
            dcdz1.w = ( 3.0f * c1.w - 4.0f * c1.z + c1.y) * inv2dz;
        }

        const float4 advC0 = u0*((c1 - c_xm)*inv2dx) + vc0*((cyp0 - cym0)*inv2dy) + wc0*dcdz0;
        __stcs(&o[5*FS4 + b0 + rc_], make_float4(-advC0.x, -advC0.y, -advC0.z, -advC0.w));
        const float4 advC1 = u1*((c_xq - c0)*inv2dx) + vc1*((cyp1 - cym1)*inv2dy) + wc1*dcdz1;
        __stcs(&o[5*FS4 + b1 + rc_], make_float4(-advC1.x, -advC1.y, -advC1.z, -advC1.w));
    }
}
} // namespace

extern "C" void kernel_launch(void* const* d_in, const int* in_sizes, int n_in,
                              void* d_out, int out_size)
{
    const float4* s = (const float4*)d_in[0];
    float4* o = (float4*)d_out;
    dim3 block(32, 8, 1);               // 256 threads
    dim3 grid(NY / 8, NX / 2, 1);       // 32 × 128 blocks, 2 x-points per thread
    rbx2_kernel<<<grid, block>>>(s, o);
}

// round 11
// speedup vs baseline: 1.0105x; 1.0105x over previous
#include <cuda_runtime.h>

namespace {
constexpr int NX = 256, NY = 256, NZ = 128;
constexpr int NZ4 = NZ / 4, XS4 = NY * NZ4, FS4 = NX * XS4;

constexpr float CVc = 717.0f;
constexpr float MUc = 1.8e-5f, KTHc = 0.025f, Gc = 9.8f;
constexpr float Rg  = 287.0f;

constexpr double DXd = 1.0 / NX, DYd = 1.0 / NY, DZd = 1.0 / (NZ - 1);
constexpr float inv2dx = (float)(0.5 / DXd);
constexpr float inv2dy = (float)(0.5 / DYd);
constexpr float inv2dz = (float)(0.5 / DZd);
constexpr float invdx2 = (float)(1.0 / (DXd * DXd));
constexpr float invdy2 = (float)(1.0 / (DYd * DYd));
constexpr float invdz2 = (float)(1.0 / (DZd * DZd));
constexpr float kTco   = KTHc / CVc;

__device__ __forceinline__ float4 operator+(float4 a, float4 b){ return make_float4(a.x+b.x, a.y+b.y, a.z+b.z, a.w+b.w); }
__device__ __forceinline__ float4 operator-(float4 a, float4 b){ return make_float4(a.x-b.x, a.y-b.y, a.z-b.z, a.w-b.w); }
__device__ __forceinline__ float4 operator*(float4 a, float4 b){ return make_float4(a.x*b.x, a.y*b.y, a.z*b.z, a.w*b.w); }
__device__ __forceinline__ float4 operator*(float4 a, float s){ return make_float4(a.x*s, a.y*s, a.z*s, a.w*s); }
__device__ __forceinline__ float4 operator*(float s, float4 a){ return a * s; }

__device__ __forceinline__ float4 zm_of(float4 a){
    float p = __shfl_up_sync(0xffffffffu, a.w, 1);
    return make_float4(p, a.x, a.y, a.z);
}
__device__ __forceinline__ float4 zp_of(float4 a){
    float n = __shfl_down_sync(0xffffffffu, a.x, 1);
    return make_float4(a.y, a.z, a.w, n);
}
__device__ __forceinline__ float4 inv4(float4 a){
    return make_float4(1.0f/a.x, 1.0f/a.y, 1.0f/a.z, 1.0f/a.w);
}
__device__ __forceinline__ float4 maskwall(float4 v, bool lo, bool hi){
    if (lo) v.x = 0.0f;
    if (hi) v.w = 0.0f;
    return v;
}

__global__ __launch_bounds__(256, 2)
void rbx2_kernel(const float4* __restrict__ s, float4* __restrict__ o)
{
    const int lane = threadIdx.x;                     // z chunk (4 z per lane)
    const int y  = (blockIdx.x << 3) | threadIdx.y;   // 8 y rows per block
    const int x0 = blockIdx.y << 1;                   // 2 x-points per thread

    const int bxm = ((x0 + NX - 1) & (NX - 1)) * XS4;
    const int b0  = x0 * XS4;
    const int b1  = (x0 + 1) * XS4;
    const int bxq = ((x0 + 2) & (NX - 1)) * XS4;

    const int rc_  = y * NZ4 + lane;
    const int rym_ = ((y + NY - 1) & (NY - 1)) * NZ4 + lane;
    const int ryp_ = ((y + 1)      & (NY - 1)) * NZ4 + lane;

    const bool lo = (lane == 0);
    const bool hi = (lane == 31);

    // ================= phase 1a: rho, T -> p, dp*, rinv, drou, u planes =================
    float4 u_xm, u0, u1, u_xq;                 // persist into u phase
    float4 rinv0, rinv1, Tc0, Tc1;
    float4 dpdx0, dpdx1, dpdy0, dpdy1, dpdz0, dpdz1;
    {
        const float4 r_xm = s[3*FS4 + bxm + rc_], r_0 = s[3*FS4 + b0 + rc_];
        const float4 r_1  = s[3*FS4 + b1  + rc_], r_xq = s[3*FS4 + bxq + rc_];
        const float4 T_xm = s[4*FS4 + bxm + rc_];
        Tc0 = s[4*FS4 + b0 + rc_];
        Tc1 = s[4*FS4 + b1 + rc_];
        const float4 T_xq = s[4*FS4 + bxq + rc_];

        u_xm = s[0*FS4 + bxm + rc_]; u0 = s[0*FS4 + b0 + rc_];
        u1   = s[0*FS4 + b1  + rc_]; u_xq = s[0*FS4 + bxq + rc_];

        // continuity (x-flux only)
        o[3*FS4 + b0 + rc_] = (r_xm * u_xm - r_1 * u1) * inv2dx;
        o[3*FS4 + b1 + rc_] = (r_0  * u0   - r_xq * u_xq) * inv2dx;

        rinv0 = inv4(r_0);
        rinv1 = inv4(r_1);

        const float4 p_xm = (Rg) * r_xm * T_xm;
        const float4 p0   = (Rg) * r_0  * Tc0;
        const float4 p1   = (Rg) * r_1  * Tc1;
        const float4 p_xq = (Rg) * r_xq * T_xq;

        dpdx0 = (p1   - p_xm) * inv2dx;
        dpdx1 = (p_xq - p0)   * inv2dx;
        dpdz0 = (zp_of(p0) - zm_of(p0)) * inv2dz;
        dpdz1 = (zp_of(p1) - zm_of(p1)) * inv2dz;

        // y-pressure (load r,T at y-neighbors, form p, drop)
        float4 ra = s[3*FS4 + b0 + rym_], Ta = s[4*FS4 + b0 + rym_];
        float4 rb = s[3*FS4 + b0 + ryp_], Tb = s[4*FS4 + b0 + ryp_];
        dpdy0 = (rb * Tb - ra * Ta) * (Rg * inv2dy);
        ra = s[3*FS4 + b1 + rym_]; Ta = s[4*FS4 + b1 + rym_];
        rb = s[3*FS4 + b1 + ryp_]; Tb = s[4*FS4 + b1 + ryp_];
        dpdy1 = (rb * Tb - ra * Ta) * (Rg * inv2dy);
    }

    // ================= phase 1b: dT (reload T neighbors — L1 hot) + v,w centers ========
    float4 vc0, vc1, wc0, wc1;                 // persist as advection velocities
    {
        vc0 = s[1*FS4 + b0 + rc_]; vc1 = s[1*FS4 + b1 + rc_];
        wc0 = s[2*FS4 + b0 + rc_]; wc1 = s[2*FS4 + b1 + rc_];

        const float4 Txm  = s[4*FS4 + bxm + rc_], Txq  = s[4*FS4 + bxq + rc_];
        const float4 Tym0 = s[4*FS4 + b0 + rym_], Typ0 = s[4*FS4 + b0 + ryp_];
        const float4 Tym1 = s[4*FS4 + b1 + rym_], Typ1 = s[4*FS4 + b1 + ryp_];
        const float4 Tzm0 = zm_of(Tc0), Tzp0 = zp_of(Tc0);
        const float4 Tzm1 = zm_of(Tc1), Tzp1 = zp_of(Tc1);

        const float4 lapT0 = (Tc1 + Txm - Tc0*2.0f)*invdx2 + (Typ0 + Tym0 - Tc0*2.0f)*invdy2 + (Tzp0 + Tzm0 - Tc0*2.0f)*invdz2;
        const float4 advT0 = u0*((Tc1 - Txm)*inv2dx) + vc0*((Typ0 - Tym0)*inv2dy) + wc0*((Tzp0 - Tzm0)*inv2dz);
        o[4*FS4 + b0 + rc_] = maskwall((lapT0 * kTco) * rinv0 - advT0, lo, hi);

        const float4 lapT1 = (Txq + Tc0 - Tc1*2.0f)*invdx2 + (Typ1 + Tym1 - Tc1*2.0f)*invdy2 + (Tzp1 + Tzm1 - Tc1*2.0f)*invdz2;
        const float4 advT1 = u1*((Txq - Tc0)*inv2dx) + vc1*((Typ1 - Tym1)*inv2dy) + wc1*((Tzp1 - Tzm1)*inv2dz);
        o[4*FS4 + b1 + rc_] = maskwall((lapT1 * kTco) * rinv1 - advT1, lo, hi);
    }

    // ================= phase 2: u =================
    {
        const float4 uym0 = s[0*FS4 + b0 + rym_], uyp0 = s[0*FS4 + b0 + ryp_];
        const float4 uym1 = s[0*FS4 + b1 + rym_], uyp1 = s[0*FS4 + b1 + ryp_];
        const float4 uzm0 = zm_of(u0), uzp0 = zp_of(u0);
        const float4 uzm1 = zm_of(u1), uzp1 = zp_of(u1);

        const float4 lapU0 = (u1 + u_xm - u0*2.0f)*invdx2 + (uyp0 + uym0 - u0*2.0f)*invdy2 + (uzp0 + uzm0 - u0*2.0f)*invdz2;
        const float4 advU0 = u0*((u1 - u_xm)*inv2dx) + vc0*((uyp0 - uym0)*inv2dy) + wc0*((uzp0 - uzm0)*inv2dz);
        o[0*FS4 + b0 + rc_] = maskwall((lapU0 * MUc - dpdx0) * rinv0 - advU0, lo, hi);

        const float4 lapU1 = (u_xq + u0 - u1*2.0f)*invdx2 + (uyp1 + uym1 - u1*2.0f)*invdy2 + (uzp1 + uzm1 - u1*2.0f)*invdz2;
        const float4 advU1 = u1*((u_xq - u0)*inv2dx) + vc1*((uyp1 - uym1)*inv2dy) + wc1*((uzp1 - uzm1)*inv2dz);
        o[0*FS4 + b1 + rc_] = maskwall((lapU1 * MUc - dpdx1) * rinv1 - advU1, lo, hi);
    }

    // ================= phase 3: v =================
    {
        const float4 v_xm = s[1*FS4 + bxm + rc_], v_xq = s[1*FS4 + bxq + rc_];
        const float4 vym0 = s[1*FS4 + b0 + rym_], vyp0 = s[1*FS4 + b0 + ryp_];
        const float4 vym1 = s[1*FS4 + b1 + rym_], vyp1 = s[1*FS4 + b1 + ryp_];
        const float4 vzm0 = zm_of(vc0), vzp0 = zp_of(vc0);
        const float4 vzm1 = zm_of(vc1), vzp1 = zp_of(vc1);

        const float4 lapV0 = (vc1 + v_xm - vc0*2.0f)*invdx2 + (vyp0 + vym0 - vc0*2.0f)*invdy2 + (vzp0 + vzm0 - vc0*2.0f)*invdz2;
        const float4 advV0 = u0*((vc1 - v_xm)*inv2dx) + vc0*((vyp0 - vym0)*inv2dy) + wc0*((vzp0 - vzm0)*inv2dz);
        o[1*FS4 + b0 + rc_] = maskwall((lapV0 * MUc - dpdy0) * rinv0 - advV0, lo, hi);

        const float4 lapV1 = (v_xq + vc0 - vc1*2.0f)*invdx2 + (vyp1 + vym1 - vc1*2.0f)*invdy2 + (vzp1 + vzm1 - vc1*2.0f)*invdz2;
        const float4 advV1 = u1*((v_xq - vc0)*inv2dx) + vc1*((vyp1 - vym1)*inv2dy) + wc1*((vzp1 - vzm1)*inv2dz);
        o[1*FS4 + b1 + rc_] = maskwall((lapV1 * MUc - dpdy1) * rinv1 - advV1, lo, hi);
    }

    // ================= phase 4: w  ((-G*rho)/rho == -G) =================
    {
        const float4 w_xm = s[2*FS4 + bxm + rc_], w_xq = s[2*FS4 + bxq + rc_];
        const float4 wym0 = s[2*FS4 + b0 + rym_], wyp0 = s[2*FS4 + b0 + ryp_];
        const float4 wym1 = s[2*FS4 + b1 + rym_], wyp1 = s[2*FS4 + b1 + ryp_];
        const float4 wzm0 = zm_of(wc0), wzp0 = zp_of(wc0);
        const float4 wzm1 = zm_of(wc1), wzp1 = zp_of(wc1);

        const float4 lapW0 = (wc1 + w_xm - wc0*2.0f)*invdx2 + (wyp0 + wym0 - wc0*2.0f)*invdy2 + (wzp0 + wzm0 - wc0*2.0f)*invdz2;
        const float4 advW0 = u0*((wc1 - w_xm)*inv2dx) + vc0*((wyp0 - wym0)*inv2dy) + wc0*((wzp0 - wzm0)*inv2dz);
        float4 dw0 = (lapW0 * MUc - dpdz0) * rinv0 - advW0;
        dw0 = make_float4(dw0.x - Gc, dw0.y - Gc, dw0.z - Gc, dw0.w - Gc);
        o[2*FS4 + b0 + rc_] = maskwall(dw0, lo, hi);

        const float4 lapW1 = (w_xq + wc0 - wc1*2.0f)*invdx2 + (wyp1 + wym1 - wc1*2.0f)*invdy2 + (wzp1 + wzm1 - wc1*2.0f)*invdz2;
        const float4 advW1 = u1*((w_xq - wc0)*inv2dx) + vc1*((wyp1 - wym1)*inv2dy) + wc1*((wzp1 - wzm1)*inv2dz);
        float4 dw1 = (lapW1 * MUc - dpdz1) * rinv1 - advW1;
        dw1 = make_float4(dw1.x - Gc, dw1.y - Gc, dw1.z - Gc, dw1.w - Gc);
        o[2*FS4 + b1 + rc_] = maskwall(dw1, lo, hi);
    }

    // ================= phase 5: c (one-sided z at walls, NOT masked) =================
    {
        const float4 c_xm = s[5*FS4 + bxm + rc_], c0 = s[5*FS4 + b0 + rc_];
        const float4 c1   = s[5*FS4 + b1  + rc_], c_xq = s[5*FS4 + bxq + rc_];
        const float4 cym0 = s[5*FS4 + b0 + rym_], cyp0 = s[5*FS4 + b0 + ryp_];
        const float4 cym1 = s[5*FS4 + b1 + rym_], cyp1 = s[5*FS4 + b1 + ryp_];

        const float4 czm0 = zm_of(c0), czp0 = zp_of(c0);
        const float4 czm1 = zm_of(c1), czp1 = zp_of(c1);

        float4 dcdz0 = (czp0 - czm0) * inv2dz;
        float4 dcdz1 = (czp1 - czm1) * inv2dz;
        if (lo) {
            dcdz0.x = (-3.0f * c0.x + 4.0f * c0.y - c0.z) * inv2dz;
            dcdz1.x = (-3.0f * c1.x + 4.0f * c1.y - c1.z) * inv2dz;
        }
        if (hi) {
            dcdz0.w = ( 3.0f * c0.w - 4.0f * c0.z + c0.y) * inv2dz;
            dcdz1.w = ( 3.0f * c1.w - 4.0f * c1.z + c1.y) * inv2dz;
        }

        const float4 advC0 = u0*((c1 - c_xm)*inv2dx) + vc0*((cyp0 - cym0)*inv2dy) + wc0*dcdz0;
        o[5*FS4 + b0 + rc_] = make_float4(-advC0.x, -advC0.y, -advC0.z, -advC0.w);
        const float4 advC1 = u1*((c_xq - c0)*inv2dx) + vc1*((cyp1 - cym1)*inv2dy) + wc1*dcdz1;
        o[5*FS4 + b1 + rc_] = make_float4(-advC1.x, -advC1.y, -advC1.z, -advC1.w);
    }
}
} // namespace

extern "C" void kernel_launch(void* const* d_in, const int* in_sizes, int n_in,
                              void* d_out, int out_size)
{
    const float4* s = (const float4*)d_in[0];
    float4* o = (float4*)d_out;
    dim3 block(32, 8, 1);               // 256 threads
    dim3 grid(NY / 8, NX / 2, 1);       // 32 × 128 blocks, 2 x-points per thread
    rbx2_kernel<<<grid, block>>>(s, o);
}

// round 12
// speedup vs baseline: 1.0542x; 1.0432x over previous
#include <cuda_runtime.h>

namespace {
constexpr int NX = 256, NY = 256, NZ = 128;
constexpr int NZ4 = NZ / 4, XS4 = NY * NZ4, FS4 = NX * XS4;

constexpr float CVc = 717.0f;
constexpr float MUc = 1.8e-5f, KTHc = 0.025f, Gc = 9.8f;
constexpr float Rg  = 287.0f;

constexpr double DXd = 1.0 / NX, DYd = 1.0 / NY, DZd = 1.0 / (NZ - 1);
constexpr float inv2dx = (float)(0.5 / DXd);
constexpr float inv2dy = (float)(0.5 / DYd);
constexpr float inv2dz = (float)(0.5 / DZd);
constexpr float invdx2 = (float)(1.0 / (DXd * DXd));
constexpr float invdy2 = (float)(1.0 / (DYd * DYd));
constexpr float invdz2 = (float)(1.0 / (DZd * DZd));
constexpr float kTco   = KTHc / CVc;

__device__ __forceinline__ float4 operator+(float4 a, float4 b){ return make_float4(a.x+b.x, a.y+b.y, a.z+b.z, a.w+b.w); }
__device__ __forceinline__ float4 operator-(float4 a, float4 b){ return make_float4(a.x-b.x, a.y-b.y, a.z-b.z, a.w-b.w); }
__device__ __forceinline__ float4 operator*(float4 a, float4 b){ return make_float4(a.x*b.x, a.y*b.y, a.z*b.z, a.w*b.w); }
__device__ __forceinline__ float4 operator*(float4 a, float s){ return make_float4(a.x*s, a.y*s, a.z*s, a.w*s); }
__device__ __forceinline__ float4 operator*(float s, float4 a){ return a * s; }

__device__ __forceinline__ float4 zm_of(float4 a){
    float p = __shfl_up_sync(0xffffffffu, a.w, 1);
    return make_float4(p, a.x, a.y, a.z);
}
__device__ __forceinline__ float4 zp_of(float4 a){
    float n = __shfl_down_sync(0xffffffffu, a.x, 1);
    return make_float4(a.y, a.z, a.w, n);
}
__device__ __forceinline__ float4 inv4(float4 a){
    return make_float4(1.0f/a.x, 1.0f/a.y, 1.0f/a.z, 1.0f/a.w);
}
__device__ __forceinline__ float4 maskwall(float4 v, bool lo, bool hi){
    if (lo) v.x = 0.0f;
    if (hi) v.w = 0.0f;
    return v;
}

__global__ __launch_bounds__(128, 4)
void rby2_kernel(const float4* __restrict__ s, float4* __restrict__ o)
{
    const int lane = threadIdx.x;                       // z chunk (4 z per lane)
    const int ty   = threadIdx.y;                       // 0..3 (each owns a y-pair)
    const int y0   = (blockIdx.x << 3) + (ty << 1);     // even row of the pair
    const int y1   = y0 + 1;
    const int x    = blockIdx.y;

    const int pxm = ((x + NX - 1) & (NX - 1)) * XS4;
    const int pc  = x * XS4;
    const int pxp = ((x + 1) & (NX - 1)) * XS4;

    const int iym  = pc + ((y0 + NY - 1) & (NY - 1)) * NZ4 + lane;
    const int i0   = pc + y0 * NZ4 + lane;
    const int i1   = pc + y1 * NZ4 + lane;
    const int iyp  = pc + ((y1 + 1) & (NY - 1)) * NZ4 + lane;
    const int ixm0 = pxm + y0 * NZ4 + lane;
    const int ixm1 = pxm + y1 * NZ4 + lane;
    const int ixp0 = pxp + y0 * NZ4 + lane;
    const int ixp1 = pxp + y1 * NZ4 + lane;

    const bool lo = (lane == 0);
    const bool hi = (lane == 31);

    float4 rinv0, rinv1;
    float4 dpdx0, dpdx1, dpdy0, dpdy1, dpdz0, dpdz1;
    float4 uxm0, uxm1, uxp0, uxp1;          // kept for u phase
    float4 uc0, uc1, vc0, vc1, wc0, wc1;    // advection velocities

    // ========= phase 1: rho + T -> rinv, pressure gradients, drou, dT =========
    {
        const float4 rym = s[3*FS4+iym], r0 = s[3*FS4+i0], r1 = s[3*FS4+i1], ryp = s[3*FS4+iyp];
        const float4 rxm0 = s[3*FS4+ixm0], rxm1 = s[3*FS4+ixm1];
        const float4 rxp0 = s[3*FS4+ixp0], rxp1 = s[3*FS4+ixp1];
        const float4 Tym = s[4*FS4+iym], T0 = s[4*FS4+i0], T1 = s[4*FS4+i1], Typ = s[4*FS4+iyp];
        const float4 Txm0 = s[4*FS4+ixm0], Txm1 = s[4*FS4+ixm1];
        const float4 Txp0 = s[4*FS4+ixp0], Txp1 = s[4*FS4+ixp1];

        rinv0 = inv4(r0);
        rinv1 = inv4(r1);

        dpdx0 = (rxp0 * Txp0 - rxm0 * Txm0) * (Rg * inv2dx);
        dpdx1 = (rxp1 * Txp1 - rxm1 * Txm1) * (Rg * inv2dx);
        dpdy0 = (r1  * T1  - rym * Tym) * (Rg * inv2dy);
        dpdy1 = (ryp * Typ - r0  * T0 ) * (Rg * inv2dy);
        const float4 p0 = r0 * T0;
        const float4 p1 = r1 * T1;
        dpdz0 = (zp_of(p0) - zm_of(p0)) * (Rg * inv2dz);
        dpdz1 = (zp_of(p1) - zm_of(p1)) * (Rg * inv2dz);

        // u x-neighbors for drou (kept live into the u phase)
        uxm0 = s[0*FS4+ixm0]; uxm1 = s[0*FS4+ixm1];
        uxp0 = s[0*FS4+ixp0]; uxp1 = s[0*FS4+ixp1];
        __stcs(&o[3*FS4 + i0], (rxm0 * uxm0 - rxp0 * uxp0) * inv2dx);
        __stcs(&o[3*FS4 + i1], (rxm1 * uxm1 - rxp1 * uxp1) * inv2dx);

        // advection velocities (centers)
        uc0 = s[0*FS4+i0]; uc1 = s[0*FS4+i1];
        vc0 = s[1*FS4+i0]; vc1 = s[1*FS4+i1];
        wc0 = s[2*FS4+i0]; wc1 = s[2*FS4+i1];

        // dT (T fully resident)
        const float4 Tzm0 = zm_of(T0), Tzp0 = zp_of(T0);
        const float4 Tzm1 = zm_of(T1), Tzp1 = zp_of(T1);

        const float4 lapT0 = (Txp0 + Txm0 - T0*2.0f)*invdx2 + (T1 + Tym - T0*2.0f)*invdy2 + (Tzp0 + Tzm0 - T0*2.0f)*invdz2;
        const float4 advT0 = uc0*((Txp0 - Txm0)*inv2dx) + vc0*((T1 - Tym)*inv2dy) + wc0*((Tzp0 - Tzm0)*inv2dz);
        __stcs(&o[4*FS4 + i0], maskwall((lapT0 * kTco) * rinv0 - advT0, lo, hi));

        const float4 lapT1 = (Txp1 + Txm1 - T1*2.0f)*invdx2 + (Typ + T0 - T1*2.0f)*invdy2 + (Tzp1 + Tzm1 - T1*2.0f)*invdz2;
        const float4 advT1 = uc1*((Txp1 - Txm1)*inv2dx) + vc1*((Typ - T0)*inv2dy) + wc1*((Tzp1 - Tzm1)*inv2dz);
        __stcs(&o[4*FS4 + i1], maskwall((lapT1 * kTco) * rinv1 - advT1, lo, hi));
    }

    // ========= phase 2: u (x-neighbors already live; y-halo 2 loads) =========
    {
        const float4 uym = s[0*FS4+iym], uyp = s[0*FS4+iyp];
        const float4 uzm0 = zm_of(uc0), uzp0 = zp_of(uc0);
        const float4 uzm1 = zm_of(uc1), uzp1 = zp_of(uc1);

        const float4 lapU0 = (uxp0 + uxm0 - uc0*2.0f)*invdx2 + (uc1 + uym - uc0*2.0f)*invdy2 + (uzp0 + uzm0 - uc0*2.0f)*invdz2;
        const float4 advU0 = uc0*((uxp0 - uxm0)*inv2dx) + vc0*((uc1 - uym)*inv2dy) + wc0*((uzp0 - uzm0)*inv2dz);
        __stcs(&o[0*FS4 + i0], maskwall((lapU0 * MUc - dpdx0) * rinv0 - advU0, lo, hi));

        const float4 lapU1 = (uxp1 + uxm1 - uc1*2.0f)*invdx2 + (uyp + uc0 - uc1*2.0f)*invdy2 + (uzp1 + uzm1 - uc1*2.0f)*invdz2;
        const float4 advU1 = uc1*((uxp1 - uxm1)*inv2dx) + vc1*((uyp - uc0)*inv2dy) + wc1*((uzp1 - uzm1)*inv2dz);
        __stcs(&o[0*FS4 + i1], maskwall((lapU1 * MUc - dpdx1) * rinv1 - advU1, lo, hi));
    }

    // ========= phase 3: v =========
    {
        const float4 vym = s[1*FS4+iym], vyp = s[1*FS4+iyp];
        const float4 vxm0 = s[1*FS4+ixm0], vxm1 = s[1*FS4+ixm1];
        const float4 vxp0 = s[1*FS4+ixp0], vxp1 = s[1*FS4+ixp1];
        const float4 vzm0 = zm_of(vc0), vzp0 = zp_of(vc0);
        const float4 vzm1 = zm_of(vc1), vzp1 = zp_of(vc1);

        const float4 lapV0 = (vxp0 + vxm0 - vc0*2.0f)*invdx2 + (vc1 + vym - vc0*2.0f)*invdy2 + (vzp0 + vzm0 - vc0*2.0f)*invdz2;
        const float4 advV0 = uc0*((vxp0 - vxm0)*inv2dx) + vc0*((vc1 - vym)*inv2dy) + wc0*((vzp0 - vzm0)*inv2dz);
        __stcs(&o[1*FS4 + i0], maskwall((lapV0 * MUc - dpdy0) * rinv0 - advV0, lo, hi));

        const float4 lapV1 = (vxp1 + vxm1 - vc1*2.0f)*invdx2 + (vyp + vc0 - vc1*2.0f)*invdy2 + (vzp1 + vzm1 - vc1*2.0f)*invdz2;
        const float4 advV1 = uc1*((vxp1 - vxm1)*inv2dx) + vc1*((vyp - vc0)*inv2dy) + wc1*((vzp1 - vzm1)*inv2dz);
        __stcs(&o[1*FS4 + i1], maskwall((lapV1 * MUc - dpdy1) * rinv1 - advV1, lo, hi));
    }

    // ========= phase 4: w  ((-G*rho)/rho == -G) =========
    {
        const float4 wym = s[2*FS4+iym], wyp = s[2*FS4+iyp];
        const float4 wxm0 = s[2*FS4+ixm0], wxm1 = s[2*FS4+ixm1];
        const float4 wxp0 = s[2*FS4+ixp0], wxp1 = s[2*FS4+ixp1];
        const float4 wzm0 = zm_of(wc0), wzp0 = zp_of(wc0);
        const float4 wzm1 = zm_of(wc1), wzp1 = zp_of(wc1);

        const float4 lapW0 = (wxp0 + wxm0 - wc0*2.0f)*invdx2 + (wc1 + wym - wc0*2.0f)*invdy2 + (wzp0 + wzm0 - wc0*2.0f)*invdz2;
        const float4 advW0 = uc0*((wxp0 - wxm0)*inv2dx) + vc0*((wc1 - wym)*inv2dy) + wc0*((wzp0 - wzm0)*inv2dz);
        float4 dw0 = (lapW0 * MUc - dpdz0) * rinv0 - advW0;
        dw0 = make_float4(dw0.x - Gc, dw0.y - Gc, dw0.z - Gc, dw0.w - Gc);
        __stcs(&o[2*FS4 + i0], maskwall(dw0, lo, hi));

        const float4 lapW1 = (wxp1 + wxm1 - wc1*2.0f)*invdx2 + (wyp + wc0 - wc1*2.0f)*invdy2 + (wzp1 + wzm1 - wc1*2.0f)*invdz2;
        const float4 advW1 = uc1*((wxp1 - wxm1)*inv2dx) + vc1*((wyp - wc0)*inv2dy) + wc1*((wzp1 - wzm1)*inv2dz);
        float4 dw1 = (lapW1 * MUc - dpdz1) * rinv1 - advW1;
        dw1 = make_float4(dw1.x - Gc, dw1.y - Gc, dw1.z - Gc, dw1.w - Gc);
        __stcs(&o[2*FS4 + i1], maskwall(dw1, lo, hi));
    }

    // ========= phase 5: c (one-sided z at walls, NOT masked) =========
    {
        const float4 cym = s[5*FS4+iym], c0 = s[5*FS4+i0], c1 = s[5*FS4+i1], cyp = s[5*FS4+iyp];
        const float4 cxm0 = s[5*FS4+ixm0], cxm1 = s[5*FS4+ixm1];
        const float4 cxp0 = s[5*FS4+ixp0], cxp1 = s[5*FS4+ixp1];

        const float4 czm0 = zm_of(c0), czp0 = zp_of(c0);
        const float4 czm1 = zm_of(c1), czp1 = zp_of(c1);

        float4 dcdz0 = (czp0 - czm0) * inv2dz;
        float4 dcdz1 = (czp1 - czm1) * inv2dz;
        if (lo) {
            dcdz0.x = (-3.0f * c0.x + 4.0f * c0.y - c0.z) * inv2dz;
            dcdz1.x = (-3.0f * c1.x + 4.0f * c1.y - c1.z) * inv2dz;
        }
        if (hi) {
            dcdz0.w = ( 3.0f * c0.w - 4.0f * c0.z + c0.y) * inv2dz;
            dcdz1.w = ( 3.0f * c1.w - 4.0f * c1.z + c1.y) * inv2dz;
        }

        const float4 advC0 = uc0*((cxp0 - cxm0)*inv2dx) + vc0*((c1 - cym)*inv2dy) + wc0*dcdz0;
        __stcs(&o[5*FS4 + i0], make_float4(-advC0.x, -advC0.y, -advC0.z, -advC0.w));
        const float4 advC1 = uc1*((cxp1 - cxm1)*inv2dx) + vc1*((cyp - c0)*inv2dy) + wc1*dcdz1;
        __stcs(&o[5*FS4 + i1], make_float4(-advC1.x, -advC1.y, -advC1.z, -advC1.w));
    }
}
} // namespace

extern "C" void kernel_launch(void* const* d_in, const int* in_sizes, int n_in,
                              void* d_out, int out_size)
{
    const float4* s = (const float4*)d_in[0];
    float4* o = (float4*)d_out;
    dim3 block(32, 4, 1);               // 128 threads: 32 z-chunks × 4 y-pairs (8 rows)
    dim3 grid(NY / 8, NX, 1);           // 32 × 256 blocks
    rby2_kernel<<<grid, block>>>(s, o);
}